// round 11
// baseline (speedup 1.0000x reference)
#include <cuda_runtime.h>
#include <cuda_bf16.h>
#include <math.h>
#include <stdint.h>

// Problem constants
#define BB 4
#define SS 512
#define DD 512
#define HH 8
#define DKV 64
#define DFF 2048
#define LL 6
#define NTOK (BB*SS)          // 2048
#define EPS 1e-5f

// Scratch (device globals; no allocation allowed)
__device__ __align__(128) float g_h[NTOK*DD];     // fp32 residual stream
__device__ __align__(128) float g_hr[NTOK*DD];    // tf32-rounded copy (GEMM A input)
__device__ __align__(128) float g_q[NTOK*DD];
__device__ __align__(128) float g_k[NTOK*DD];
__device__ __align__(128) float g_v[NTOK*DD];
__device__ __align__(128) float g_ctx[NTOK*DD];
__device__ __align__(128) float g_tmp[NTOK*DD];
__device__ __align__(128) float g_ff[NTOK*DFF];

__device__ __forceinline__ uint32_t tf32u(float x) {
    uint32_t u;
    asm("cvt.rna.tf32.f32 %0, %1;" : "=r"(u) : "f"(x));
    return u;
}
__device__ __forceinline__ float tf32f(float x) { return __uint_as_float(tf32u(x)); }

// ---------------------------------------------------------------------------
// Embedding: h = emb[x] + pe (fp32) ; hr = tf32round(h)
// ---------------------------------------------------------------------------
__global__ void embed_kernel(const int* __restrict__ x,
                             const float* __restrict__ emb,
                             const float* __restrict__ pe,
                             float* __restrict__ h,
                             float* __restrict__ hr)
{
    int tok = blockIdx.x;
    int s = tok & (SS-1);
    int id = x[tok];
    int t = threadIdx.x; // 0..127
    const float4* e4 = reinterpret_cast<const float4*>(emb + (size_t)id*DD);
    const float4* p4 = reinterpret_cast<const float4*>(pe + (size_t)s*DD);
    float4 ev = e4[t], pv = p4[t];
    float4 r; r.x=ev.x+pv.x; r.y=ev.y+pv.y; r.z=ev.z+pv.z; r.w=ev.w+pv.w;
    reinterpret_cast<float4*>(h + (size_t)tok*DD)[t] = r;
    float4 rr; rr.x=tf32f(r.x); rr.y=tf32f(r.y); rr.z=tf32f(r.z); rr.w=tf32f(r.w);
    reinterpret_cast<float4*>(hr + (size_t)tok*DD)[t] = rr;
}

__device__ __forceinline__ float gelu_f(float x) {
    return 0.5f * x * (1.0f + tanhf(0.7978845608028654f * (x + 0.044715f*x*x*x)));
}

__device__ __forceinline__ void mma_tf32(float* c, const uint32_t* a, const uint32_t* b) {
    asm volatile(
        "mma.sync.aligned.m16n8k8.row.col.f32.tf32.tf32.f32 "
        "{%0,%1,%2,%3}, {%4,%5,%6,%7}, {%8,%9}, {%0,%1,%2,%3};"
        : "+f"(c[0]), "+f"(c[1]), "+f"(c[2]), "+f"(c[3])
        : "r"(a[0]), "r"(a[1]), "r"(a[2]), "r"(a[3]), "r"(b[0]), "r"(b[1]));
}

__device__ __forceinline__ void cp16(void* smem_dst, const void* gsrc) {
    uint32_t s = (uint32_t)__cvta_generic_to_shared(smem_dst);
    asm volatile("cp.async.cg.shared.global [%0], [%1], 16;" :: "r"(s), "l"(gsrc));
}
#define CP_COMMIT() asm volatile("cp.async.commit_group;")
#define CP_WAIT2()  asm volatile("cp.async.wait_group 2;")
#define CP_WAIT1()  asm volatile("cp.async.wait_group 1;")
#define CP_WAIT0()  asm volatile("cp.async.wait_group 0;")

// smem layout sizes (floats)
#define A_TILE_F (128*20)          // [128][20]
#define B_TILE_F(BN) (16*((BN)+8)) // [16][BN+8]

__device__ __forceinline__ uint32_t ldraw(const float& p) { return __float_as_uint(p); }

// ---------------------------------------------------------------------------
// Pipelined TF32 GEMM: C[M,N] = A[M,K] @ B[K,N] (+bias)(+res)(+gelu)(+round)
// A is pre-rounded to tf32 by its producer -> raw-bit fragment loads (no CVT).
// B (weights) converted at fragment load.
// CTA tile 128 x BN, BK=16, 4-stage cp.async, 1 sync/iter, 256 threads.
// ---------------------------------------------------------------------------
template<int BN, int WR>
__global__ __launch_bounds__(256, 2) void gemm_tf32p(
    const float* __restrict__ A, int lda,
    const float* __restrict__ B0, const float* __restrict__ B1, const float* __restrict__ B2,
    int ldb,
    const float* __restrict__ bias0, const float* __restrict__ bias1, const float* __restrict__ bias2,
    const float* __restrict__ res,
    float* __restrict__ C0, float* __restrict__ C1, float* __restrict__ C2,
    int ldc, int K, int act, int round_out)
{
    constexpr int MI = 128/(WR*16);
    constexpr int WC = 8/WR;
    constexpr int NI = BN/(WC*8);

    int z = blockIdx.z;
    const float* B    = (z == 0) ? B0    : ((z == 1) ? B1    : B2);
    const float* bias = (z == 0) ? bias0 : ((z == 1) ? bias1 : bias2);
    float*       C    = (z == 0) ? C0    : ((z == 1) ? C1    : C2);

    extern __shared__ float dsm[];
    float (*As)[128][20]  = reinterpret_cast<float(*)[128][20]>(dsm);
    float (*Bs)[16][BN+8] = reinterpret_cast<float(*)[16][BN+8]>(dsm + 4*A_TILE_F);

    int tid  = threadIdx.x;
    int lane = tid & 31, warp = tid >> 5;
    int g    = lane >> 2, tig = lane & 3;
    int mw   = warp % WR, nw = warp / WR;
    int wm   = mw * (MI*16);
    int wn   = nw * (NI*8);
    int m0   = blockIdx.y * 128, n0 = blockIdx.x * BN;

    int arow = tid >> 1, acol = (tid & 1) * 8;
    int brow = tid >> 4;
    int bcol = (BN == 64) ? (tid & 15) * 4 : (tid & 15) * 8;

    const float* Aptr = A + (size_t)(m0 + arow) * lda + acol;
    const float* Bptr = B + (size_t)brow * ldb + n0 + bcol;

    float acc[MI][NI][4];
#pragma unroll
    for (int mi = 0; mi < MI; mi++)
#pragma unroll
        for (int ni = 0; ni < NI; ni++)
#pragma unroll
            for (int r = 0; r < 4; r++) acc[mi][ni][r] = 0.f;

    int nk = K >> 4;

#pragma unroll
    for (int s = 0; s < 3; s++) {
        int k0 = s * 16;
        cp16(&As[s][arow][acol],     Aptr + k0);
        cp16(&As[s][arow][acol + 4], Aptr + k0 + 4);
        cp16(&Bs[s][brow][bcol],     Bptr + (size_t)k0 * ldb);
        if (BN == 128)
            cp16(&Bs[s][brow][bcol + 4], Bptr + (size_t)k0 * ldb + 4);
        CP_COMMIT();
    }

    for (int it = 0; it < nk; it++) {
        if (it + 2 < nk) CP_WAIT2();
        else if (it + 1 < nk) CP_WAIT1();
        else CP_WAIT0();
        __syncthreads();
        int s = it & 3;
#pragma unroll
        for (int kk = 0; kk < 16; kk += 8) {
            uint32_t af[MI][4], bf[NI][2];
#pragma unroll
            for (int mi = 0; mi < MI; mi++) {
                int r = wm + mi*16 + g;
                af[mi][0] = ldraw(As[s][r    ][kk+tig  ]);
                af[mi][1] = ldraw(As[s][r + 8][kk+tig  ]);
                af[mi][2] = ldraw(As[s][r    ][kk+tig+4]);
                af[mi][3] = ldraw(As[s][r + 8][kk+tig+4]);
            }
#pragma unroll
            for (int ni = 0; ni < NI; ni++) {
                int cc = wn + ni*8 + g;
                bf[ni][0] = tf32u(Bs[s][kk+tig  ][cc]);
                bf[ni][1] = tf32u(Bs[s][kk+tig+4][cc]);
            }
#pragma unroll
            for (int mi = 0; mi < MI; mi++)
#pragma unroll
                for (int ni = 0; ni < NI; ni++)
                    mma_tf32(acc[mi][ni], af[mi], bf[ni]);
        }
        int nx = it + 3;
        if (nx < nk) {
            int sn = nx & 3;
            int k0 = nx * 16;
            cp16(&As[sn][arow][acol],     Aptr + k0);
            cp16(&As[sn][arow][acol + 4], Aptr + k0 + 4);
            cp16(&Bs[sn][brow][bcol],     Bptr + (size_t)k0 * ldb);
            if (BN == 128)
                cp16(&Bs[sn][brow][bcol + 4], Bptr + (size_t)k0 * ldb + 4);
            CP_COMMIT();
        }
    }

#pragma unroll
    for (int mi = 0; mi < MI; mi++) {
        int row0 = m0 + wm + mi*16 + g;
#pragma unroll
        for (int ni = 0; ni < NI; ni++) {
            int col = n0 + wn + ni*8 + 2*tig;
            float b0 = 0.f, b1 = 0.f;
            if (bias) { b0 = bias[col]; b1 = bias[col+1]; }
            float v0 = acc[mi][ni][0] + b0;
            float v1 = acc[mi][ni][1] + b1;
            float v2 = acc[mi][ni][2] + b0;
            float v3 = acc[mi][ni][3] + b1;
            if (res) {
                const float* r0p = res + (size_t)row0 * ldc + col;
                const float* r1p = res + (size_t)(row0+8) * ldc + col;
                v0 += r0p[0]; v1 += r0p[1];
                v2 += r1p[0]; v3 += r1p[1];
            }
            if (act) {
                v0 = gelu_f(v0); v1 = gelu_f(v1);
                v2 = gelu_f(v2); v3 = gelu_f(v3);
            }
            if (round_out) {
                v0 = tf32f(v0); v1 = tf32f(v1);
                v2 = tf32f(v2); v3 = tf32f(v3);
            }
            *reinterpret_cast<float2*>(C + (size_t)row0 * ldc + col)     = make_float2(v0, v1);
            *reinterpret_cast<float2*>(C + (size_t)(row0+8) * ldc + col) = make_float2(v2, v3);
        }
    }
}

// ---------------------------------------------------------------------------
// FUSED score GEMM + softmax: per (b,h) P = softmax(mask(Q @ K^T * scale))
// CTA = 32 q-rows x FULL 512 kv-cols, K=64. 256 threads, 8 warps (2m x 4n),
// warp tile 16x128. B streamed in 4 chunks of 128 rows, 2-stage cp.async.
// Row softmax in-register: tig-shfl + cross-warp smem reduction.
// Q,K pre-rounded tf32 -> raw fragment loads.
// grid (16 mtile, 32 bh)
// ---------------------------------------------------------------------------
__global__ __launch_bounds__(256, 2) void score_soft(
    const float* __restrict__ Q,
    const float* __restrict__ Kmat,
    const int* __restrict__ x,
    float* __restrict__ attn, int l, float scale)
{
    extern __shared__ float dsm[];
    float (*As)[68]       = reinterpret_cast<float(*)[68]>(dsm);                  // [32][68]
    float (*Bs)[128][68]  = reinterpret_cast<float(*)[128][68]>(dsm + 32*68);     // [2][128][68]
    float* redm = dsm + 32*68 + 2*128*68;   // [32][4]
    float* reds = redm + 128;               // [32][4]

    int tid  = threadIdx.x;
    int lane = tid & 31, warp = tid >> 5;
    int g    = lane >> 2, tig = lane & 3;
    int mw   = warp & 1, nw = warp >> 1;
    int wml  = mw * 16;
    int zz = blockIdx.y;
    int b = zz >> 3, hh = zz & 7;
    int m0 = blockIdx.x * 32;

    const float* Abase = Q    + (size_t)b*SS*DD + hh*DKV;
    const float* Bbase = Kmat + (size_t)b*SS*DD + hh*DKV;
    float* out = attn + (((size_t)b*LL + l)*HH + hh) * (size_t)(SS*SS);

    // A loader: 32 rows x 64 k, 8 floats/thread (2 cp16)
    int arow = tid >> 3, acol = (tid & 7) * 8;
    // B loader: 128 rows x 64 k per chunk, 32 floats/thread (8 cp16)
    int brow = tid >> 1, bcol = (tid & 1) * 32;

    float acc[16][4];
#pragma unroll
    for (int ni = 0; ni < 16; ni++)
#pragma unroll
        for (int r = 0; r < 4; r++) acc[ni][r] = 0.f;

    // prologue: A + B chunk 0
    {
        const float* Ap = Abase + (size_t)(m0 + arow) * DD + acol;
        cp16(&As[arow][acol],     Ap);
        cp16(&As[arow][acol + 4], Ap + 4);
        const float* Bp = Bbase + (size_t)brow * DD + bcol;
#pragma unroll
        for (int c2 = 0; c2 < 8; c2++)
            cp16(&Bs[0][brow][bcol + c2*4], Bp + c2*4);
        CP_COMMIT();
    }

#pragma unroll
    for (int ch = 0; ch < 4; ch++) {
        CP_WAIT0();
        __syncthreads();
        if (ch < 3) {
            // prefetch chunk ch+1 into stage (ch+1)&1 (its last consumer
            // finished a full iteration ago; sync above makes this race-free)
            const float* Bp = Bbase + (size_t)((ch+1)*128 + brow) * DD + bcol;
            int st = (ch + 1) & 1;
#pragma unroll
            for (int c2 = 0; c2 < 8; c2++)
                cp16(&Bs[st][brow][bcol + c2*4], Bp + c2*4);
            CP_COMMIT();
        }
        int s = ch & 1;
#pragma unroll
        for (int kk = 0; kk < 64; kk += 8) {
            uint32_t af[4], bf[4][2];
            int r = wml + g;
            af[0] = ldraw(As[r    ][kk+tig  ]);
            af[1] = ldraw(As[r + 8][kk+tig  ]);
            af[2] = ldraw(As[r    ][kk+tig+4]);
            af[3] = ldraw(As[r + 8][kk+tig+4]);
#pragma unroll
            for (int nl = 0; nl < 4; nl++) {
                int cc = nw*32 + nl*8 + g;
                bf[nl][0] = ldraw(Bs[s][cc][kk+tig  ]);
                bf[nl][1] = ldraw(Bs[s][cc][kk+tig+4]);
            }
#pragma unroll
            for (int nl = 0; nl < 4; nl++)
                mma_tf32(acc[ch*4 + nl], af, bf[nl]);
        }
    }

    // ---- fused softmax over the 512-wide rows ----
    const int* xb = x + b*SS;
    int lr0 = wml + g, lr1 = lr0 + 8;

    float mx0 = -1e30f, mx1 = -1e30f;
#pragma unroll
    for (int ni = 0; ni < 16; ni++) {
        int col = (ni >> 2)*128 + nw*32 + (ni & 3)*8 + 2*tig;
        bool k0m = (xb[col]   == 0);
        bool k1m = (xb[col+1] == 0);
        acc[ni][0] = k0m ? -1e9f : acc[ni][0]*scale;
        acc[ni][1] = k1m ? -1e9f : acc[ni][1]*scale;
        acc[ni][2] = k0m ? -1e9f : acc[ni][2]*scale;
        acc[ni][3] = k1m ? -1e9f : acc[ni][3]*scale;
        mx0 = fmaxf(mx0, fmaxf(acc[ni][0], acc[ni][1]));
        mx1 = fmaxf(mx1, fmaxf(acc[ni][2], acc[ni][3]));
    }
    mx0 = fmaxf(mx0, __shfl_xor_sync(0xffffffffu, mx0, 1));
    mx0 = fmaxf(mx0, __shfl_xor_sync(0xffffffffu, mx0, 2));
    mx1 = fmaxf(mx1, __shfl_xor_sync(0xffffffffu, mx1, 1));
    mx1 = fmaxf(mx1, __shfl_xor_sync(0xffffffffu, mx1, 2));
    if (tig == 0) { redm[lr0*4 + nw] = mx0; redm[lr1*4 + nw] = mx1; }
    __syncthreads();
    mx0 = fmaxf(fmaxf(redm[lr0*4], redm[lr0*4+1]), fmaxf(redm[lr0*4+2], redm[lr0*4+3]));
    mx1 = fmaxf(fmaxf(redm[lr1*4], redm[lr1*4+1]), fmaxf(redm[lr1*4+2], redm[lr1*4+3]));

    float s0 = 0.f, s1 = 0.f;
#pragma unroll
    for (int ni = 0; ni < 16; ni++) {
        acc[ni][0] = __expf(acc[ni][0] - mx0);
        acc[ni][1] = __expf(acc[ni][1] - mx0);
        acc[ni][2] = __expf(acc[ni][2] - mx1);
        acc[ni][3] = __expf(acc[ni][3] - mx1);
        s0 += acc[ni][0] + acc[ni][1];
        s1 += acc[ni][2] + acc[ni][3];
    }
    s0 += __shfl_xor_sync(0xffffffffu, s0, 1);
    s0 += __shfl_xor_sync(0xffffffffu, s0, 2);
    s1 += __shfl_xor_sync(0xffffffffu, s1, 1);
    s1 += __shfl_xor_sync(0xffffffffu, s1, 2);
    if (tig == 0) { reds[lr0*4 + nw] = s0; reds[lr1*4 + nw] = s1; }
    __syncthreads();
    s0 = reds[lr0*4] + reds[lr0*4+1] + reds[lr0*4+2] + reds[lr0*4+3];
    s1 = reds[lr1*4] + reds[lr1*4+1] + reds[lr1*4+2] + reds[lr1*4+3];
    float inv0 = 1.0f / s0, inv1 = 1.0f / s1;

    int r0 = m0 + lr0, r1 = m0 + lr1;
#pragma unroll
    for (int ni = 0; ni < 16; ni++) {
        int col = (ni >> 2)*128 + nw*32 + (ni & 3)*8 + 2*tig;
        *reinterpret_cast<float2*>(out + (size_t)r0*SS + col)
            = make_float2(acc[ni][0]*inv0, acc[ni][1]*inv0);
        *reinterpret_cast<float2*>(out + (size_t)r1*SS + col)
            = make_float2(acc[ni][2]*inv1, acc[ni][3]*inv1);
    }
}

// ---------------------------------------------------------------------------
// Pipelined TF32 ctx GEMM: per (b,h) C[512,64] = P[512,512] @ V[512,64]
// P (attn) converted at load; V pre-rounded -> raw. Output rounded (feeds WO).
// CTA 128x64, warps 4m x 2n. grid (4 mtile, 32 bh)
// ---------------------------------------------------------------------------
__global__ __launch_bounds__(256, 2) void ctx_tf32p(
    const float* __restrict__ attn,
    const float* __restrict__ V,
    float* __restrict__ C, int l)
{
    constexpr int MI = 2, NI = 4;

    extern __shared__ float dsm[];
    float (*As)[128][20] = reinterpret_cast<float(*)[128][20]>(dsm);
    float (*Bs)[16][72]  = reinterpret_cast<float(*)[16][72]>(dsm + 4*A_TILE_F);

    int tid  = threadIdx.x;
    int lane = tid & 31, warp = tid >> 5;
    int g    = lane >> 2, tig = lane & 3;
    int wm   = (warp & 3) * 32;
    int wn   = (warp >> 2) * 32;
    int zz = blockIdx.y;
    int b = zz >> 3, hh = zz & 7;
    int m0 = blockIdx.x * 128;

    const float* Abase = attn + (((size_t)b*LL + l)*HH + hh) * (size_t)(SS*SS);
    const float* Bbase = V + (size_t)b*SS*DD + hh*DKV;
    float* Cb = C + (size_t)b*SS*DD + hh*DKV;

    int arow = tid >> 1, acol = (tid & 1) * 8;
    int brow = tid >> 4, bcol = (tid & 15) * 4;

    const float* Aptr = Abase + (size_t)(m0 + arow) * SS + acol;
    const float* Bptr = Bbase + (size_t)brow * DD + bcol;

    float acc[MI][NI][4];
#pragma unroll
    for (int mi = 0; mi < MI; mi++)
#pragma unroll
        for (int ni = 0; ni < NI; ni++)
#pragma unroll
            for (int r = 0; r < 4; r++) acc[mi][ni][r] = 0.f;

    const int nk = SS >> 4; // 32

#pragma unroll
    for (int s = 0; s < 3; s++) {
        int k0 = s * 16;
        cp16(&As[s][arow][acol],     Aptr + k0);
        cp16(&As[s][arow][acol + 4], Aptr + k0 + 4);
        cp16(&Bs[s][brow][bcol],     Bptr + (size_t)k0 * DD);
        CP_COMMIT();
    }

    for (int it = 0; it < nk; it++) {
        if (it + 2 < nk) CP_WAIT2();
        else if (it + 1 < nk) CP_WAIT1();
        else CP_WAIT0();
        __syncthreads();
        int s = it & 3;
#pragma unroll
        for (int kk = 0; kk < 16; kk += 8) {
            uint32_t af[MI][4], bf[NI][2];
#pragma unroll
            for (int mi = 0; mi < MI; mi++) {
                int r = wm + mi*16 + g;
                af[mi][0] = tf32u(As[s][r    ][kk+tig  ]);
                af[mi][1] = tf32u(As[s][r + 8][kk+tig  ]);
                af[mi][2] = tf32u(As[s][r    ][kk+tig+4]);
                af[mi][3] = tf32u(As[s][r + 8][kk+tig+4]);
            }
#pragma unroll
            for (int ni = 0; ni < NI; ni++) {
                int cc = wn + ni*8 + g;
                bf[ni][0] = ldraw(Bs[s][kk+tig  ][cc]);
                bf[ni][1] = ldraw(Bs[s][kk+tig+4][cc]);
            }
#pragma unroll
            for (int mi = 0; mi < MI; mi++)
#pragma unroll
                for (int ni = 0; ni < NI; ni++)
                    mma_tf32(acc[mi][ni], af[mi], bf[ni]);
        }
        int nx = it + 3;
        if (nx < nk) {
            int sn = nx & 3;
            int k0 = nx * 16;
            cp16(&As[sn][arow][acol],     Aptr + k0);
            cp16(&As[sn][arow][acol + 4], Aptr + k0 + 4);
            cp16(&Bs[sn][brow][bcol],     Bptr + (size_t)k0 * DD);
            CP_COMMIT();
        }
    }

#pragma unroll
    for (int mi = 0; mi < MI; mi++) {
        int row0 = m0 + wm + mi*16 + g;
#pragma unroll
        for (int ni = 0; ni < NI; ni++) {
            int col = wn + ni*8 + 2*tig;
            *reinterpret_cast<float2*>(Cb + (size_t)row0 * DD + col)
                = make_float2(tf32f(acc[mi][ni][0]), tf32f(acc[mi][ni][1]));
            *reinterpret_cast<float2*>(Cb + (size_t)(row0+8) * DD + col)
                = make_float2(tf32f(acc[mi][ni][2]), tf32f(acc[mi][ni][3]));
        }
    }
}

// ---------------------------------------------------------------------------
// LayerNorm: 2 rows per 256-thread block, float4 per thread.
// Writes fp32 out (+ optional tf32-rounded copy).
// ---------------------------------------------------------------------------
__global__ __launch_bounds__(256) void ln_kernel(
    const float* __restrict__ in,
    const float* __restrict__ g,
    const float* __restrict__ bta,
    float* __restrict__ outh,
    float* __restrict__ outhr)
{
    __shared__ float red[2][8];
    int half = threadIdx.x >> 7;           // 0 or 1
    int row  = blockIdx.x * 2 + half;
    int t    = threadIdx.x & 127;
    int lane = t & 31, wid = t >> 5;       // wid 0..3 within half

    const float4* p = reinterpret_cast<const float4*>(in + (size_t)row*DD);
    float4 v = p[t];

    float s  = v.x + v.y + v.z + v.w;
    float sq = v.x*v.x + v.y*v.y + v.z*v.z + v.w*v.w;
#pragma unroll
    for (int o = 16; o > 0; o >>= 1) {
        s  += __shfl_xor_sync(0xffffffffu, s,  o);
        sq += __shfl_xor_sync(0xffffffffu, sq, o);
    }
    if (lane == 0) { red[half][wid] = s; red[half][4+wid] = sq; }
    __syncthreads();
    s  = red[half][0]+red[half][1]+red[half][2]+red[half][3];
    sq = red[half][4]+red[half][5]+red[half][6]+red[half][7];
    float mu = s * (1.0f/DD);
    float var = sq * (1.0f/DD) - mu*mu;
    float rstd = rsqrtf(var + EPS);

    float4 gg = reinterpret_cast<const float4*>(g)[t];
    float4 bb = reinterpret_cast<const float4*>(bta)[t];
    float4 r;
    r.x = (v.x - mu) * rstd * gg.x + bb.x;
    r.y = (v.y - mu) * rstd * gg.y + bb.y;
    r.z = (v.z - mu) * rstd * gg.z + bb.z;
    r.w = (v.w - mu) * rstd * gg.w + bb.w;
    reinterpret_cast<float4*>(outh + (size_t)row*DD)[t] = r;
    if (outhr) {
        float4 rr; rr.x=tf32f(r.x); rr.y=tf32f(r.y); rr.z=tf32f(r.z); rr.w=tf32f(r.w);
        reinterpret_cast<float4*>(outhr + (size_t)row*DD)[t] = rr;
    }
}

// ---------------------------------------------------------------------------
extern "C" void kernel_launch(void* const* d_in, const int* in_sizes, int n_in,
                              void* d_out, int out_size)
{
    const int*   x    = (const int*)  d_in[0];
    const float* emb  = (const float*)d_in[1];
    const float* pe   = (const float*)d_in[2];
    const float* WQ   = (const float*)d_in[3];
    const float* bQ   = (const float*)d_in[4];
    const float* WK   = (const float*)d_in[5];
    const float* bK   = (const float*)d_in[6];
    const float* WV   = (const float*)d_in[7];
    const float* bV   = (const float*)d_in[8];
    const float* WO   = (const float*)d_in[9];
    const float* bO   = (const float*)d_in[10];
    const float* ln1g = (const float*)d_in[11];
    const float* ln1b = (const float*)d_in[12];
    const float* W1   = (const float*)d_in[13];
    const float* b1   = (const float*)d_in[14];
    const float* W2   = (const float*)d_in[15];
    const float* b2   = (const float*)d_in[16];
    const float* ln2g = (const float*)d_in[17];
    const float* ln2b = (const float*)d_in[18];

    float* out  = (float*)d_out;
    float* attn = out + (size_t)NTOK*DD;

    float *h, *hr, *q, *k, *v, *ctx, *tmp, *ff;
    cudaGetSymbolAddress((void**)&h,   g_h);
    cudaGetSymbolAddress((void**)&hr,  g_hr);
    cudaGetSymbolAddress((void**)&q,   g_q);
    cudaGetSymbolAddress((void**)&k,   g_k);
    cudaGetSymbolAddress((void**)&v,   g_v);
    cudaGetSymbolAddress((void**)&ctx, g_ctx);
    cudaGetSymbolAddress((void**)&tmp, g_tmp);
    cudaGetSymbolAddress((void**)&ff,  g_ff);

    // dynamic smem sizes (bytes)
    const int SM_D128 = (4*A_TILE_F + 4*B_TILE_F(128)) * 4;  // 75776
    const int SM_D64  = (4*A_TILE_F + 4*B_TILE_F(64))  * 4;  // 59392
    const int SM_FS   = (32*68 + 2*128*68 + 256) * 4;        // 79360

    static int attr_done = 0;
    if (!attr_done) {
        cudaFuncSetAttribute(gemm_tf32p<128,2>, cudaFuncAttributeMaxDynamicSharedMemorySize, SM_D128);
        cudaFuncSetAttribute(gemm_tf32p<64,4>,  cudaFuncAttributeMaxDynamicSharedMemorySize, SM_D64);
        cudaFuncSetAttribute(score_soft,        cudaFuncAttributeMaxDynamicSharedMemorySize, SM_FS);
        cudaFuncSetAttribute(ctx_tf32p,         cudaFuncAttributeMaxDynamicSharedMemorySize, SM_D64);
        attr_done = 1;
    }

    const float scale = 0.125f;

    embed_kernel<<<NTOK, 128>>>(x, emb, pe, h, hr);

    for (int l = 0; l < LL; l++) {
        const float* wq = WQ + (size_t)l*DD*DD;
        const float* wk = WK + (size_t)l*DD*DD;
        const float* wv = WV + (size_t)l*DD*DD;
        const float* wo = WO + (size_t)l*DD*DD;
        const float* w1 = W1 + (size_t)l*DD*DFF;
        const float* w2 = W2 + (size_t)l*DFF*DD;

        // fused QKV: A = hr (rounded), outputs rounded (feed score/ctx raw)
        gemm_tf32p<128,2><<<dim3(4,16,3), 256, SM_D128>>>(hr, DD,
            wq, wk, wv, DD,
            bQ + l*DD, bK + l*DD, bV + l*DD,
            nullptr,
            q, k, v, DD, DD, 0, 1);

        // fused score + softmax (writes normalized probs directly)
        score_soft<<<dim3(16,32), 256, SM_FS>>>(q, k, x, attn, l, scale);

        ctx_tf32p<<<dim3(4,32), 256, SM_D64>>>(attn, v, ctx, l);

        // WO: A = ctx (rounded), residual = fp32 h, out fp32 (feeds LN only)
        gemm_tf32p<64,4><<<dim3(8,16,1), 256, SM_D64>>>(ctx, DD,
            wo, wo, wo, DD,
            bO + l*DD, bO + l*DD, bO + l*DD,
            h,
            tmp, tmp, tmp, DD, DD, 0, 0);
        ln_kernel<<<NTOK/2, 256>>>(tmp, ln1g + l*DD, ln1b + l*DD, h, hr);

        // FFN1: A = hr, output ff rounded (feeds FFN2 A raw)
        gemm_tf32p<128,2><<<dim3(16,16,1), 256, SM_D128>>>(hr, DD,
            w1, w1, w1, DFF,
            b1 + l*DFF, b1 + l*DFF, b1 + l*DFF,
            nullptr,
            ff, ff, ff, DFF, DD, 1, 1);

        // FFN2: A = ff (rounded), residual = fp32 h, out fp32
        gemm_tf32p<64,4><<<dim3(8,16,1), 256, SM_D64>>>(ff, DFF,
            w2, w2, w2, DD,
            b2 + l*DD, b2 + l*DD, b2 + l*DD,
            h,
            tmp, tmp, tmp, DD, DFF, 0, 0);

        if (l == LL-1) {
            ln_kernel<<<NTOK/2, 256>>>(tmp, ln2g + l*DD, ln2b + l*DD, out, nullptr);
        } else {
            ln_kernel<<<NTOK/2, 256>>>(tmp, ln2g + l*DD, ln2b + l*DD, h, hr);
        }
    }
}

// round 12
// speedup vs baseline: 1.0215x; 1.0215x over previous
#include <cuda_runtime.h>
#include <cuda_bf16.h>
#include <math.h>
#include <stdint.h>

// Problem constants
#define BB 4
#define SS 512
#define DD 512
#define HH 8
#define DKV 64
#define DFF 2048
#define LL 6
#define NTOK (BB*SS)          // 2048
#define EPS 1e-5f

// Scratch (device globals; no allocation allowed)
__device__ __align__(128) float g_h[NTOK*DD];     // fp32 residual stream
__device__ __align__(128) float g_hr[NTOK*DD];    // tf32-rounded copy (GEMM A input)
__device__ __align__(128) float g_q[NTOK*DD];
__device__ __align__(128) float g_k[NTOK*DD];
__device__ __align__(128) float g_v[NTOK*DD];
__device__ __align__(128) float g_ctx[NTOK*DD];
__device__ __align__(128) float g_tmp[NTOK*DD];
__device__ __align__(128) float g_ff[NTOK*DFF];

__device__ __forceinline__ uint32_t tf32u(float x) {
    uint32_t u;
    asm("cvt.rna.tf32.f32 %0, %1;" : "=r"(u) : "f"(x));
    return u;
}
__device__ __forceinline__ float tf32f(float x) { return __uint_as_float(tf32u(x)); }

// ---------------------------------------------------------------------------
// Embedding: h = emb[x] + pe (fp32) ; hr = tf32round(h)
// ---------------------------------------------------------------------------
__global__ void embed_kernel(const int* __restrict__ x,
                             const float* __restrict__ emb,
                             const float* __restrict__ pe,
                             float* __restrict__ h,
                             float* __restrict__ hr)
{
    int tok = blockIdx.x;
    int s = tok & (SS-1);
    int id = x[tok];
    int t = threadIdx.x; // 0..127
    const float4* e4 = reinterpret_cast<const float4*>(emb + (size_t)id*DD);
    const float4* p4 = reinterpret_cast<const float4*>(pe + (size_t)s*DD);
    float4 ev = e4[t], pv = p4[t];
    float4 r; r.x=ev.x+pv.x; r.y=ev.y+pv.y; r.z=ev.z+pv.z; r.w=ev.w+pv.w;
    reinterpret_cast<float4*>(h + (size_t)tok*DD)[t] = r;
    float4 rr; rr.x=tf32f(r.x); rr.y=tf32f(r.y); rr.z=tf32f(r.z); rr.w=tf32f(r.w);
    reinterpret_cast<float4*>(hr + (size_t)tok*DD)[t] = rr;
}

__device__ __forceinline__ float gelu_f(float x) {
    return 0.5f * x * (1.0f + tanhf(0.7978845608028654f * (x + 0.044715f*x*x*x)));
}

__device__ __forceinline__ void mma_tf32(float* c, const uint32_t* a, const uint32_t* b) {
    asm volatile(
        "mma.sync.aligned.m16n8k8.row.col.f32.tf32.tf32.f32 "
        "{%0,%1,%2,%3}, {%4,%5,%6,%7}, {%8,%9}, {%0,%1,%2,%3};"
        : "+f"(c[0]), "+f"(c[1]), "+f"(c[2]), "+f"(c[3])
        : "r"(a[0]), "r"(a[1]), "r"(a[2]), "r"(a[3]), "r"(b[0]), "r"(b[1]));
}

__device__ __forceinline__ void cp16(void* smem_dst, const void* gsrc) {
    uint32_t s = (uint32_t)__cvta_generic_to_shared(smem_dst);
    asm volatile("cp.async.cg.shared.global [%0], [%1], 16;" :: "r"(s), "l"(gsrc));
}
#define CP_COMMIT() asm volatile("cp.async.commit_group;")
#define CP_WAIT2()  asm volatile("cp.async.wait_group 2;")
#define CP_WAIT1()  asm volatile("cp.async.wait_group 1;")
#define CP_WAIT0()  asm volatile("cp.async.wait_group 0;")

__device__ __forceinline__ uint32_t ldraw(const float& p) { return __float_as_uint(p); }

// ---------------------------------------------------------------------------
// Pipelined TF32 GEMM: C[M,N] = A[M,K] @ B[K,N] (+bias)(+res)(+gelu)(+round)
// A pre-rounded tf32 -> raw fragment loads. B converted at fragment load.
// CTA tile BM x BN, BK=16, 4-stage cp.async, 1 sync/iter, 256 threads.
// ---------------------------------------------------------------------------
template<int BM, int BN, int WR, int MINB>
__global__ __launch_bounds__(256, MINB) void gemm_tf32p(
    const float* __restrict__ A, int lda,
    const float* __restrict__ B0, const float* __restrict__ B1, const float* __restrict__ B2,
    int ldb,
    const float* __restrict__ bias0, const float* __restrict__ bias1, const float* __restrict__ bias2,
    const float* __restrict__ res,
    float* __restrict__ C0, float* __restrict__ C1, float* __restrict__ C2,
    int ldc, int K, int act, int round_out)
{
    constexpr int MI = BM/(WR*16);
    constexpr int WC = 8/WR;
    constexpr int NI = BN/(WC*8);

    int z = blockIdx.z;
    const float* B    = (z == 0) ? B0    : ((z == 1) ? B1    : B2);
    const float* bias = (z == 0) ? bias0 : ((z == 1) ? bias1 : bias2);
    float*       C    = (z == 0) ? C0    : ((z == 1) ? C1    : C2);

    extern __shared__ float dsm[];
    float (*As)[BM][20]   = reinterpret_cast<float(*)[BM][20]>(dsm);
    float (*Bs)[16][BN+8] = reinterpret_cast<float(*)[16][BN+8]>(dsm + 4*BM*20);

    int tid  = threadIdx.x;
    int lane = tid & 31, warp = tid >> 5;
    int g    = lane >> 2, tig = lane & 3;
    int mw   = warp % WR, nw = warp / WR;
    int wm   = mw * (MI*16);
    int wn   = nw * (NI*8);
    int m0   = blockIdx.y * BM, n0 = blockIdx.x * BN;

    // loaders (BM x 16 A-tile; 16 x BN B-tile; 256 threads)
    int arow = (BM == 128) ? (tid >> 1) : (tid >> 2);
    int acol = (BM == 128) ? ((tid & 1) * 8) : ((tid & 3) * 4);
    int brow = tid >> 4;
    int bcol = (BN == 64) ? (tid & 15) * 4 : (tid & 15) * 8;

    const float* Aptr = A + (size_t)(m0 + arow) * lda + acol;
    const float* Bptr = B + (size_t)brow * ldb + n0 + bcol;

    float acc[MI][NI][4];
#pragma unroll
    for (int mi = 0; mi < MI; mi++)
#pragma unroll
        for (int ni = 0; ni < NI; ni++)
#pragma unroll
            for (int r = 0; r < 4; r++) acc[mi][ni][r] = 0.f;

    int nk = K >> 4;

#pragma unroll
    for (int s = 0; s < 3; s++) {
        int k0 = s * 16;
        cp16(&As[s][arow][acol], Aptr + k0);
        if (BM == 128)
            cp16(&As[s][arow][acol + 4], Aptr + k0 + 4);
        cp16(&Bs[s][brow][bcol], Bptr + (size_t)k0 * ldb);
        if (BN == 128)
            cp16(&Bs[s][brow][bcol + 4], Bptr + (size_t)k0 * ldb + 4);
        CP_COMMIT();
    }

    for (int it = 0; it < nk; it++) {
        if (it + 2 < nk) CP_WAIT2();
        else if (it + 1 < nk) CP_WAIT1();
        else CP_WAIT0();
        __syncthreads();
        int s = it & 3;
#pragma unroll
        for (int kk = 0; kk < 16; kk += 8) {
            uint32_t af[MI][4], bf[NI][2];
#pragma unroll
            for (int mi = 0; mi < MI; mi++) {
                int r = wm + mi*16 + g;
                af[mi][0] = ldraw(As[s][r    ][kk+tig  ]);
                af[mi][1] = ldraw(As[s][r + 8][kk+tig  ]);
                af[mi][2] = ldraw(As[s][r    ][kk+tig+4]);
                af[mi][3] = ldraw(As[s][r + 8][kk+tig+4]);
            }
#pragma unroll
            for (int ni = 0; ni < NI; ni++) {
                int cc = wn + ni*8 + g;
                bf[ni][0] = tf32u(Bs[s][kk+tig  ][cc]);
                bf[ni][1] = tf32u(Bs[s][kk+tig+4][cc]);
            }
#pragma unroll
            for (int mi = 0; mi < MI; mi++)
#pragma unroll
                for (int ni = 0; ni < NI; ni++)
                    mma_tf32(acc[mi][ni], af[mi], bf[ni]);
        }
        int nx = it + 3;
        if (nx < nk) {
            int sn = nx & 3;
            int k0 = nx * 16;
            cp16(&As[sn][arow][acol], Aptr + k0);
            if (BM == 128)
                cp16(&As[sn][arow][acol + 4], Aptr + k0 + 4);
            cp16(&Bs[sn][brow][bcol], Bptr + (size_t)k0 * ldb);
            if (BN == 128)
                cp16(&Bs[sn][brow][bcol + 4], Bptr + (size_t)k0 * ldb + 4);
            CP_COMMIT();
        }
    }

#pragma unroll
    for (int mi = 0; mi < MI; mi++) {
        int row0 = m0 + wm + mi*16 + g;
#pragma unroll
        for (int ni = 0; ni < NI; ni++) {
            int col = n0 + wn + ni*8 + 2*tig;
            float b0 = 0.f, b1 = 0.f;
            if (bias) { b0 = bias[col]; b1 = bias[col+1]; }
            float v0 = acc[mi][ni][0] + b0;
            float v1 = acc[mi][ni][1] + b1;
            float v2 = acc[mi][ni][2] + b0;
            float v3 = acc[mi][ni][3] + b1;
            if (res) {
                const float* r0p = res + (size_t)row0 * ldc + col;
                const float* r1p = res + (size_t)(row0+8) * ldc + col;
                v0 += r0p[0]; v1 += r0p[1];
                v2 += r1p[0]; v3 += r1p[1];
            }
            if (act) {
                v0 = gelu_f(v0); v1 = gelu_f(v1);
                v2 = gelu_f(v2); v3 = gelu_f(v3);
            }
            if (round_out) {
                v0 = tf32f(v0); v1 = tf32f(v1);
                v2 = tf32f(v2); v3 = tf32f(v3);
            }
            *reinterpret_cast<float2*>(C + (size_t)row0 * ldc + col)     = make_float2(v0, v1);
            *reinterpret_cast<float2*>(C + (size_t)(row0+8) * ldc + col) = make_float2(v2, v3);
        }
    }
}

// ---------------------------------------------------------------------------
// Pipelined TF32 score GEMM: per (b,h) S = Q @ K^T * scale + mask
// Q,K pre-rounded -> zero CVTs. CTA 128x128, K=64, warps 2m x 4n.
// grid (4 ntile, 4 mtile, 32 bh)
// ---------------------------------------------------------------------------
__global__ __launch_bounds__(256, 2) void score_tf32p(
    const float* __restrict__ Q,
    const float* __restrict__ Kmat,
    const int* __restrict__ x,
    float* __restrict__ attn, int l, float scale)
{
    constexpr int MI = 4, NI = 4;

    extern __shared__ float dsm[];
    float (*As)[128][20] = reinterpret_cast<float(*)[128][20]>(dsm);
    float (*Bs)[128][20] = reinterpret_cast<float(*)[128][20]>(dsm + 4*128*20);

    int tid  = threadIdx.x;
    int lane = tid & 31, warp = tid >> 5;
    int g    = lane >> 2, tig = lane & 3;
    int mw   = warp & 1, nw = warp >> 1;
    int wm   = mw * 64;
    int wn   = nw * 32;
    int zz = blockIdx.z;
    int b = zz >> 3, hh = zz & 7;
    int m0 = blockIdx.y * 128, n0 = blockIdx.x * 128;

    const float* Abase = Q    + (size_t)b*SS*DD + hh*DKV;
    const float* Bbase = Kmat + (size_t)b*SS*DD + hh*DKV;
    float* out = attn + (((size_t)b*LL + l)*HH + hh) * (size_t)(SS*SS);

    int arow = tid >> 1, acol = (tid & 1) * 8;

    const float* Aptr = Abase + (size_t)(m0 + arow) * DD + acol;
    const float* Bptr = Bbase + (size_t)(n0 + arow) * DD + acol;

    float acc[MI][NI][4];
#pragma unroll
    for (int mi = 0; mi < MI; mi++)
#pragma unroll
        for (int ni = 0; ni < NI; ni++)
#pragma unroll
            for (int r = 0; r < 4; r++) acc[mi][ni][r] = 0.f;

    const int nk = DKV >> 4; // 4

#pragma unroll
    for (int s = 0; s < 3; s++) {
        int k0 = s * 16;
        cp16(&As[s][arow][acol],     Aptr + k0);
        cp16(&As[s][arow][acol + 4], Aptr + k0 + 4);
        cp16(&Bs[s][arow][acol],     Bptr + k0);
        cp16(&Bs[s][arow][acol + 4], Bptr + k0 + 4);
        CP_COMMIT();
    }

#pragma unroll
    for (int it = 0; it < nk; it++) {
        if (it + 2 < nk) CP_WAIT2();
        else if (it + 1 < nk) CP_WAIT1();
        else CP_WAIT0();
        __syncthreads();
        int s = it & 3;
#pragma unroll
        for (int kk = 0; kk < 16; kk += 8) {
            uint32_t af[MI][4], bf[NI][2];
#pragma unroll
            for (int mi = 0; mi < MI; mi++) {
                int r = wm + mi*16 + g;
                af[mi][0] = ldraw(As[s][r    ][kk+tig  ]);
                af[mi][1] = ldraw(As[s][r + 8][kk+tig  ]);
                af[mi][2] = ldraw(As[s][r    ][kk+tig+4]);
                af[mi][3] = ldraw(As[s][r + 8][kk+tig+4]);
            }
#pragma unroll
            for (int ni = 0; ni < NI; ni++) {
                int cc = wn + ni*8 + g;
                bf[ni][0] = ldraw(Bs[s][cc][kk+tig  ]);
                bf[ni][1] = ldraw(Bs[s][cc][kk+tig+4]);
            }
#pragma unroll
            for (int mi = 0; mi < MI; mi++)
#pragma unroll
                for (int ni = 0; ni < NI; ni++)
                    mma_tf32(acc[mi][ni], af[mi], bf[ni]);
        }
        int nx = it + 3;
        if (nx < nk) {
            int sn = nx & 3;
            int k0 = nx * 16;
            cp16(&As[sn][arow][acol],     Aptr + k0);
            cp16(&As[sn][arow][acol + 4], Aptr + k0 + 4);
            cp16(&Bs[sn][arow][acol],     Bptr + k0);
            cp16(&Bs[sn][arow][acol + 4], Bptr + k0 + 4);
            CP_COMMIT();
        }
    }

    const int* xb = x + b*SS;
#pragma unroll
    for (int mi = 0; mi < MI; mi++) {
        int row0 = m0 + wm + mi*16 + g;
#pragma unroll
        for (int ni = 0; ni < NI; ni++) {
            int col = n0 + wn + ni*8 + 2*tig;
            bool msk0 = (xb[col]   == 0);
            bool msk1 = (xb[col+1] == 0);
            float v0 = msk0 ? -1e9f : acc[mi][ni][0] * scale;
            float v1 = msk1 ? -1e9f : acc[mi][ni][1] * scale;
            float v2 = msk0 ? -1e9f : acc[mi][ni][2] * scale;
            float v3 = msk1 ? -1e9f : acc[mi][ni][3] * scale;
            *reinterpret_cast<float2*>(out + (size_t)row0 * SS + col)     = make_float2(v0, v1);
            *reinterpret_cast<float2*>(out + (size_t)(row0+8) * SS + col) = make_float2(v2, v3);
        }
    }
}

// ---------------------------------------------------------------------------
// Pipelined TF32 ctx GEMM: per (b,h) C[512,64] = P[512,512] @ V[512,64]
// CTA 64x64 for occupancy (grid 8x32=256). warps 4m x 2n (warp 16x32).
// P converted at load; V pre-rounded -> raw. Output rounded (feeds WO).
// ---------------------------------------------------------------------------
__global__ __launch_bounds__(256, 4) void ctx_tf32p(
    const float* __restrict__ attn,
    const float* __restrict__ V,
    float* __restrict__ C, int l)
{
    constexpr int NI = 4;

    extern __shared__ float dsm[];
    float (*As)[64][20] = reinterpret_cast<float(*)[64][20]>(dsm);
    float (*Bs)[16][72] = reinterpret_cast<float(*)[16][72]>(dsm + 4*64*20);

    int tid  = threadIdx.x;
    int lane = tid & 31, warp = tid >> 5;
    int g    = lane >> 2, tig = lane & 3;
    int wm   = (warp & 3) * 16;
    int wn   = (warp >> 2) * 32;
    int zz = blockIdx.y;
    int b = zz >> 3, hh = zz & 7;
    int m0 = blockIdx.x * 64;

    const float* Abase = attn + (((size_t)b*LL + l)*HH + hh) * (size_t)(SS*SS);
    const float* Bbase = V + (size_t)b*SS*DD + hh*DKV;
    float* Cb = C + (size_t)b*SS*DD + hh*DKV;

    int arow = tid >> 2, acol = (tid & 3) * 4;   // 64 x 16, 1 cp16/thread
    int brow = tid >> 4, bcol = (tid & 15) * 4;  // 16 x 64, 1 cp16/thread

    const float* Aptr = Abase + (size_t)(m0 + arow) * SS + acol;
    const float* Bptr = Bbase + (size_t)brow * DD + bcol;

    float acc[NI][4];
#pragma unroll
    for (int ni = 0; ni < NI; ni++)
#pragma unroll
        for (int r = 0; r < 4; r++) acc[ni][r] = 0.f;

    const int nk = SS >> 4; // 32

#pragma unroll
    for (int s = 0; s < 3; s++) {
        int k0 = s * 16;
        cp16(&As[s][arow][acol], Aptr + k0);
        cp16(&Bs[s][brow][bcol], Bptr + (size_t)k0 * DD);
        CP_COMMIT();
    }

    for (int it = 0; it < nk; it++) {
        if (it + 2 < nk) CP_WAIT2();
        else if (it + 1 < nk) CP_WAIT1();
        else CP_WAIT0();
        __syncthreads();
        int s = it & 3;
#pragma unroll
        for (int kk = 0; kk < 16; kk += 8) {
            uint32_t af[4], bf[NI][2];
            int r = wm + g;
            af[0] = tf32u(As[s][r    ][kk+tig  ]);
            af[1] = tf32u(As[s][r + 8][kk+tig  ]);
            af[2] = tf32u(As[s][r    ][kk+tig+4]);
            af[3] = tf32u(As[s][r + 8][kk+tig+4]);
#pragma unroll
            for (int ni = 0; ni < NI; ni++) {
                int cc = wn + ni*8 + g;
                bf[ni][0] = ldraw(Bs[s][kk+tig  ][cc]);
                bf[ni][1] = ldraw(Bs[s][kk+tig+4][cc]);
            }
#pragma unroll
            for (int ni = 0; ni < NI; ni++)
                mma_tf32(acc[ni], af, bf[ni]);
        }
        int nx = it + 3;
        if (nx < nk) {
            int sn = nx & 3;
            int k0 = nx * 16;
            cp16(&As[sn][arow][acol], Aptr + k0);
            cp16(&Bs[sn][brow][bcol], Bptr + (size_t)k0 * DD);
            CP_COMMIT();
        }
    }

    int row0 = m0 + wm + g;
#pragma unroll
    for (int ni = 0; ni < NI; ni++) {
        int col = wn + ni*8 + 2*tig;
        *reinterpret_cast<float2*>(Cb + (size_t)row0 * DD + col)
            = make_float2(tf32f(acc[ni][0]), tf32f(acc[ni][1]));
        *reinterpret_cast<float2*>(Cb + (size_t)(row0+8) * DD + col)
            = make_float2(tf32f(acc[ni][2]), tf32f(acc[ni][3]));
    }
}

// ---------------------------------------------------------------------------
// Softmax in-place, vectorized: 1 float4 per thread (row = 512 = 128 x 4)
// ---------------------------------------------------------------------------
__global__ __launch_bounds__(128) void softmax_kernel(float* __restrict__ attn, int l)
{
    __shared__ float red[8];
    int row = blockIdx.x;
    int b = row >> 12;
    int rem = row & 4095;
    float4* p = reinterpret_cast<float4*>(
        attn + (size_t)b*(LL*HH*SS*SS) + (size_t)l*(HH*SS*SS) + (size_t)rem*SS);
    int t = threadIdx.x;
    int lane = t & 31, wid = t >> 5;

    float4 v = p[t];

    float mx = fmaxf(fmaxf(v.x, v.y), fmaxf(v.z, v.w));
#pragma unroll
    for (int o = 16; o > 0; o >>= 1) mx = fmaxf(mx, __shfl_xor_sync(0xffffffffu, mx, o));
    if (lane == 0) red[wid] = mx;
    __syncthreads();
    mx = fmaxf(fmaxf(red[0],red[1]), fmaxf(red[2],red[3]));

    v.x = __expf(v.x - mx); v.y = __expf(v.y - mx);
    v.z = __expf(v.z - mx); v.w = __expf(v.w - mx);
    float s = v.x + v.y + v.z + v.w;
#pragma unroll
    for (int o = 16; o > 0; o >>= 1) s += __shfl_xor_sync(0xffffffffu, s, o);
    if (lane == 0) red[4 + wid] = s;
    __syncthreads();
    s = red[4] + red[5] + red[6] + red[7];
    float inv = 1.0f / s;
    v.x *= inv; v.y *= inv; v.z *= inv; v.w *= inv;
    p[t] = v;
}

// ---------------------------------------------------------------------------
// LayerNorm: 2 rows per 256-thread block, float4 per thread.
// Writes fp32 out (+ optional tf32-rounded copy).
// ---------------------------------------------------------------------------
__global__ __launch_bounds__(256) void ln_kernel(
    const float* __restrict__ in,
    const float* __restrict__ g,
    const float* __restrict__ bta,
    float* __restrict__ outh,
    float* __restrict__ outhr)
{
    __shared__ float red[2][8];
    int half = threadIdx.x >> 7;           // 0 or 1
    int row  = blockIdx.x * 2 + half;
    int t    = threadIdx.x & 127;
    int lane = t & 31, wid = t >> 5;

    const float4* p = reinterpret_cast<const float4*>(in + (size_t)row*DD);
    float4 v = p[t];

    float s  = v.x + v.y + v.z + v.w;
    float sq = v.x*v.x + v.y*v.y + v.z*v.z + v.w*v.w;
#pragma unroll
    for (int o = 16; o > 0; o >>= 1) {
        s  += __shfl_xor_sync(0xffffffffu, s,  o);
        sq += __shfl_xor_sync(0xffffffffu, sq, o);
    }
    if (lane == 0) { red[half][wid] = s; red[half][4+wid] = sq; }
    __syncthreads();
    s  = red[half][0]+red[half][1]+red[half][2]+red[half][3];
    sq = red[half][4]+red[half][5]+red[half][6]+red[half][7];
    float mu = s * (1.0f/DD);
    float var = sq * (1.0f/DD) - mu*mu;
    float rstd = rsqrtf(var + EPS);

    float4 gg = reinterpret_cast<const float4*>(g)[t];
    float4 bb = reinterpret_cast<const float4*>(bta)[t];
    float4 r;
    r.x = (v.x - mu) * rstd * gg.x + bb.x;
    r.y = (v.y - mu) * rstd * gg.y + bb.y;
    r.z = (v.z - mu) * rstd * gg.z + bb.z;
    r.w = (v.w - mu) * rstd * gg.w + bb.w;
    reinterpret_cast<float4*>(outh + (size_t)row*DD)[t] = r;
    if (outhr) {
        float4 rr; rr.x=tf32f(r.x); rr.y=tf32f(r.y); rr.z=tf32f(r.z); rr.w=tf32f(r.w);
        reinterpret_cast<float4*>(outhr + (size_t)row*DD)[t] = rr;
    }
}

// ---------------------------------------------------------------------------
extern "C" void kernel_launch(void* const* d_in, const int* in_sizes, int n_in,
                              void* d_out, int out_size)
{
    const int*   x    = (const int*)  d_in[0];
    const float* emb  = (const float*)d_in[1];
    const float* pe   = (const float*)d_in[2];
    const float* WQ   = (const float*)d_in[3];
    const float* bQ   = (const float*)d_in[4];
    const float* WK   = (const float*)d_in[5];
    const float* bK   = (const float*)d_in[6];
    const float* WV   = (const float*)d_in[7];
    const float* bV   = (const float*)d_in[8];
    const float* WO   = (const float*)d_in[9];
    const float* bO   = (const float*)d_in[10];
    const float* ln1g = (const float*)d_in[11];
    const float* ln1b = (const float*)d_in[12];
    const float* W1   = (const float*)d_in[13];
    const float* b1   = (const float*)d_in[14];
    const float* W2   = (const float*)d_in[15];
    const float* b2   = (const float*)d_in[16];
    const float* ln2g = (const float*)d_in[17];
    const float* ln2b = (const float*)d_in[18];

    float* out  = (float*)d_out;
    float* attn = out + (size_t)NTOK*DD;

    float *h, *hr, *q, *k, *v, *ctx, *tmp, *ff;
    cudaGetSymbolAddress((void**)&h,   g_h);
    cudaGetSymbolAddress((void**)&hr,  g_hr);
    cudaGetSymbolAddress((void**)&q,   g_q);
    cudaGetSymbolAddress((void**)&k,   g_k);
    cudaGetSymbolAddress((void**)&v,   g_v);
    cudaGetSymbolAddress((void**)&ctx, g_ctx);
    cudaGetSymbolAddress((void**)&tmp, g_tmp);
    cudaGetSymbolAddress((void**)&ff,  g_ff);

    // dynamic smem sizes (bytes)
    const int SM_D128 = (4*128*20 + 4*16*136) * 4;  // 75776
    const int SM_64   = (4*64*20  + 4*16*72)  * 4;  // 38912
    const int SM_SC   = (4*128*20 + 4*128*20) * 4;  // 81920

    static int attr_done = 0;
    if (!attr_done) {
        cudaFuncSetAttribute(gemm_tf32p<128,128,2,2>, cudaFuncAttributeMaxDynamicSharedMemorySize, SM_D128);
        cudaFuncSetAttribute(gemm_tf32p<64,64,4,4>,   cudaFuncAttributeMaxDynamicSharedMemorySize, SM_64);
        cudaFuncSetAttribute(score_tf32p,             cudaFuncAttributeMaxDynamicSharedMemorySize, SM_SC);
        cudaFuncSetAttribute(ctx_tf32p,               cudaFuncAttributeMaxDynamicSharedMemorySize, SM_64);
        attr_done = 1;
    }

    const float scale = 0.125f;

    embed_kernel<<<NTOK, 128>>>(x, emb, pe, h, hr);

    for (int l = 0; l < LL; l++) {
        const float* wq = WQ + (size_t)l*DD*DD;
        const float* wk = WK + (size_t)l*DD*DD;
        const float* wv = WV + (size_t)l*DD*DD;
        const float* wo = WO + (size_t)l*DD*DD;
        const float* w1 = W1 + (size_t)l*DD*DFF;
        const float* w2 = W2 + (size_t)l*DFF*DD;

        // fused QKV: A = hr (rounded), outputs rounded (feed score/ctx raw)
        gemm_tf32p<128,128,2,2><<<dim3(4,16,3), 256, SM_D128>>>(hr, DD,
            wq, wk, wv, DD,
            bQ + l*DD, bK + l*DD, bV + l*DD,
            nullptr,
            q, k, v, DD, DD, 0, 1);

        score_tf32p<<<dim3(4,4,32), 256, SM_SC>>>(q, k, x, attn, l, scale);
        softmax_kernel<<<BB*HH*SS, 128>>>(attn, l);
        ctx_tf32p<<<dim3(8,32), 256, SM_64>>>(attn, v, ctx, l);

        // WO: 64x64 tiles, grid (8,32) = 256 CTAs
        gemm_tf32p<64,64,4,4><<<dim3(8,32,1), 256, SM_64>>>(ctx, DD,
            wo, wo, wo, DD,
            bO + l*DD, bO + l*DD, bO + l*DD,
            h,
            tmp, tmp, tmp, DD, DD, 0, 0);
        ln_kernel<<<NTOK/2, 256>>>(tmp, ln1g + l*DD, ln1b + l*DD, h, hr);

        // FFN1: A = hr, output ff rounded (feeds FFN2 A raw)
        gemm_tf32p<128,128,2,2><<<dim3(16,16,1), 256, SM_D128>>>(hr, DD,
            w1, w1, w1, DFF,
            b1 + l*DFF, b1 + l*DFF, b1 + l*DFF,
            nullptr,
            ff, ff, ff, DFF, DD, 1, 1);

        // FFN2: 64x64 tiles, grid (8,32) = 256 CTAs
        gemm_tf32p<64,64,4,4><<<dim3(8,32,1), 256, SM_64>>>(ff, DFF,
            w2, w2, w2, DD,
            b2 + l*DD, b2 + l*DD, b2 + l*DD,
            h,
            tmp, tmp, tmp, DD, DFF, 0, 0);

        if (l == LL-1) {
            ln_kernel<<<NTOK/2, 256>>>(tmp, ln2g + l*DD, ln2b + l*DD, out, nullptr);
        } else {
            ln_kernel<<<NTOK/2, 256>>>(tmp, ln2g + l*DD, ln2b + l*DD, h, hr);
        }
    }
}

// round 13
// speedup vs baseline: 1.0807x; 1.0580x over previous
#include <cuda_runtime.h>
#include <cuda_bf16.h>
#include <math.h>
#include <stdint.h>

// Problem constants
#define BB 4
#define SS 512
#define DD 512
#define HH 8
#define DKV 64
#define DFF 2048
#define LL 6
#define NTOK (BB*SS)          // 2048
#define EPS 1e-5f

// Scratch (device globals; no allocation allowed)
__device__ __align__(128) float g_h[NTOK*DD];     // fp32 residual stream
__device__ __align__(128) float g_hr[NTOK*DD];    // tf32-rounded copy (GEMM A input)
__device__ __align__(128) float g_q[NTOK*DD];
__device__ __align__(128) float g_k[NTOK*DD];
__device__ __align__(128) float g_v[NTOK*DD];
__device__ __align__(128) float g_ctx[NTOK*DD];
__device__ __align__(128) float g_tmp[NTOK*DD];
__device__ __align__(128) float g_ff[NTOK*DFF];
// tf32-pre-rounded weights (same layout as inputs)
__device__ __align__(128) float g_wq[LL*DD*DD];
__device__ __align__(128) float g_wk[LL*DD*DD];
__device__ __align__(128) float g_wv[LL*DD*DD];
__device__ __align__(128) float g_wo[LL*DD*DD];
__device__ __align__(128) float g_w1[LL*DD*DFF];
__device__ __align__(128) float g_w2[LL*DFF*DD];

__device__ __forceinline__ uint32_t tf32u(float x) {
    uint32_t u;
    asm("cvt.rna.tf32.f32 %0, %1;" : "=r"(u) : "f"(x));
    return u;
}
__device__ __forceinline__ float tf32f(float x) { return __uint_as_float(tf32u(x)); }

// ---------------------------------------------------------------------------
// Weight pre-round: out = tf32round(in), elementwise float4
// ---------------------------------------------------------------------------
__global__ void roundw_kernel(const float4* __restrict__ in, float4* __restrict__ outp, int n4)
{
    int i = blockIdx.x * 256 + threadIdx.x;
    if (i < n4) {
        float4 v = in[i];
        v.x = tf32f(v.x); v.y = tf32f(v.y); v.z = tf32f(v.z); v.w = tf32f(v.w);
        outp[i] = v;
    }
}

// ---------------------------------------------------------------------------
// Embedding: h = emb[x] + pe (fp32) ; hr = tf32round(h)
// ---------------------------------------------------------------------------
__global__ void embed_kernel(const int* __restrict__ x,
                             const float* __restrict__ emb,
                             const float* __restrict__ pe,
                             float* __restrict__ h,
                             float* __restrict__ hr)
{
    int tok = blockIdx.x;
    int s = tok & (SS-1);
    int id = x[tok];
    int t = threadIdx.x; // 0..127
    const float4* e4 = reinterpret_cast<const float4*>(emb + (size_t)id*DD);
    const float4* p4 = reinterpret_cast<const float4*>(pe + (size_t)s*DD);
    float4 ev = e4[t], pv = p4[t];
    float4 r; r.x=ev.x+pv.x; r.y=ev.y+pv.y; r.z=ev.z+pv.z; r.w=ev.w+pv.w;
    reinterpret_cast<float4*>(h + (size_t)tok*DD)[t] = r;
    float4 rr; rr.x=tf32f(r.x); rr.y=tf32f(r.y); rr.z=tf32f(r.z); rr.w=tf32f(r.w);
    reinterpret_cast<float4*>(hr + (size_t)tok*DD)[t] = rr;
}

__device__ __forceinline__ float gelu_f(float x) {
    return 0.5f * x * (1.0f + tanhf(0.7978845608028654f * (x + 0.044715f*x*x*x)));
}

__device__ __forceinline__ void mma_tf32(float* c, const uint32_t* a, const uint32_t* b) {
    asm volatile(
        "mma.sync.aligned.m16n8k8.row.col.f32.tf32.tf32.f32 "
        "{%0,%1,%2,%3}, {%4,%5,%6,%7}, {%8,%9}, {%0,%1,%2,%3};"
        : "+f"(c[0]), "+f"(c[1]), "+f"(c[2]), "+f"(c[3])
        : "r"(a[0]), "r"(a[1]), "r"(a[2]), "r"(a[3]), "r"(b[0]), "r"(b[1]));
}

__device__ __forceinline__ void cp16(void* smem_dst, const void* gsrc) {
    uint32_t s = (uint32_t)__cvta_generic_to_shared(smem_dst);
    asm volatile("cp.async.cg.shared.global [%0], [%1], 16;" :: "r"(s), "l"(gsrc));
}
#define CP_COMMIT() asm volatile("cp.async.commit_group;")
#define CP_WAIT2()  asm volatile("cp.async.wait_group 2;")
#define CP_WAIT1()  asm volatile("cp.async.wait_group 1;")
#define CP_WAIT0()  asm volatile("cp.async.wait_group 0;")

__device__ __forceinline__ uint32_t ldraw(const float& p) { return __float_as_uint(p); }

// ---------------------------------------------------------------------------
// Pipelined TF32 GEMM: C[M,N] = A[M,K] @ B[K,N] (+bias)(+res)(+gelu)(+round)
// BOTH operands pre-rounded tf32 -> all-raw fragment loads (zero CVTs).
// CTA tile 128 x BN, BK=16, 4-stage cp.async, 1 sync/iter, 256 threads.
// ---------------------------------------------------------------------------
template<int BN, int WR>
__global__ __launch_bounds__(256, 2) void gemm_tf32p(
    const float* __restrict__ A, int lda,
    const float* __restrict__ B0, const float* __restrict__ B1, const float* __restrict__ B2,
    int ldb,
    const float* __restrict__ bias0, const float* __restrict__ bias1, const float* __restrict__ bias2,
    const float* __restrict__ res,
    float* __restrict__ C0, float* __restrict__ C1, float* __restrict__ C2,
    int ldc, int K, int act, int round_out)
{
    constexpr int MI = 128/(WR*16);
    constexpr int WC = 8/WR;
    constexpr int NI = BN/(WC*8);

    int z = blockIdx.z;
    const float* B    = (z == 0) ? B0    : ((z == 1) ? B1    : B2);
    const float* bias = (z == 0) ? bias0 : ((z == 1) ? bias1 : bias2);
    float*       C    = (z == 0) ? C0    : ((z == 1) ? C1    : C2);

    extern __shared__ float dsm[];
    float (*As)[128][20]  = reinterpret_cast<float(*)[128][20]>(dsm);
    float (*Bs)[16][BN+8] = reinterpret_cast<float(*)[16][BN+8]>(dsm + 4*128*20);

    int tid  = threadIdx.x;
    int lane = tid & 31, warp = tid >> 5;
    int g    = lane >> 2, tig = lane & 3;
    int mw   = warp % WR, nw = warp / WR;
    int wm   = mw * (MI*16);
    int wn   = nw * (NI*8);
    int m0   = blockIdx.y * 128, n0 = blockIdx.x * BN;

    int arow = tid >> 1, acol = (tid & 1) * 8;
    int brow = tid >> 4;
    int bcol = (BN == 64) ? (tid & 15) * 4 : (tid & 15) * 8;

    const float* Aptr = A + (size_t)(m0 + arow) * lda + acol;
    const float* Bptr = B + (size_t)brow * ldb + n0 + bcol;

    float acc[MI][NI][4];
#pragma unroll
    for (int mi = 0; mi < MI; mi++)
#pragma unroll
        for (int ni = 0; ni < NI; ni++)
#pragma unroll
            for (int r = 0; r < 4; r++) acc[mi][ni][r] = 0.f;

    int nk = K >> 4;

#pragma unroll
    for (int s = 0; s < 3; s++) {
        int k0 = s * 16;
        cp16(&As[s][arow][acol],     Aptr + k0);
        cp16(&As[s][arow][acol + 4], Aptr + k0 + 4);
        cp16(&Bs[s][brow][bcol],     Bptr + (size_t)k0 * ldb);
        if (BN == 128)
            cp16(&Bs[s][brow][bcol + 4], Bptr + (size_t)k0 * ldb + 4);
        CP_COMMIT();
    }

    for (int it = 0; it < nk; it++) {
        if (it + 2 < nk) CP_WAIT2();
        else if (it + 1 < nk) CP_WAIT1();
        else CP_WAIT0();
        __syncthreads();
        int s = it & 3;
#pragma unroll
        for (int kk = 0; kk < 16; kk += 8) {
            uint32_t af[MI][4], bf[NI][2];
#pragma unroll
            for (int mi = 0; mi < MI; mi++) {
                int r = wm + mi*16 + g;
                af[mi][0] = ldraw(As[s][r    ][kk+tig  ]);
                af[mi][1] = ldraw(As[s][r + 8][kk+tig  ]);
                af[mi][2] = ldraw(As[s][r    ][kk+tig+4]);
                af[mi][3] = ldraw(As[s][r + 8][kk+tig+4]);
            }
#pragma unroll
            for (int ni = 0; ni < NI; ni++) {
                int cc = wn + ni*8 + g;
                bf[ni][0] = ldraw(Bs[s][kk+tig  ][cc]);
                bf[ni][1] = ldraw(Bs[s][kk+tig+4][cc]);
            }
#pragma unroll
            for (int mi = 0; mi < MI; mi++)
#pragma unroll
                for (int ni = 0; ni < NI; ni++)
                    mma_tf32(acc[mi][ni], af[mi], bf[ni]);
        }
        int nx = it + 3;
        if (nx < nk) {
            int sn = nx & 3;
            int k0 = nx * 16;
            cp16(&As[sn][arow][acol],     Aptr + k0);
            cp16(&As[sn][arow][acol + 4], Aptr + k0 + 4);
            cp16(&Bs[sn][brow][bcol],     Bptr + (size_t)k0 * ldb);
            if (BN == 128)
                cp16(&Bs[sn][brow][bcol + 4], Bptr + (size_t)k0 * ldb + 4);
            CP_COMMIT();
        }
    }

#pragma unroll
    for (int mi = 0; mi < MI; mi++) {
        int row0 = m0 + wm + mi*16 + g;
#pragma unroll
        for (int ni = 0; ni < NI; ni++) {
            int col = n0 + wn + ni*8 + 2*tig;
            float b0 = 0.f, b1 = 0.f;
            if (bias) { b0 = bias[col]; b1 = bias[col+1]; }
            float v0 = acc[mi][ni][0] + b0;
            float v1 = acc[mi][ni][1] + b1;
            float v2 = acc[mi][ni][2] + b0;
            float v3 = acc[mi][ni][3] + b1;
            if (res) {
                const float* r0p = res + (size_t)row0 * ldc + col;
                const float* r1p = res + (size_t)(row0+8) * ldc + col;
                v0 += r0p[0]; v1 += r0p[1];
                v2 += r1p[0]; v3 += r1p[1];
            }
            if (act) {
                v0 = gelu_f(v0); v1 = gelu_f(v1);
                v2 = gelu_f(v2); v3 = gelu_f(v3);
            }
            if (round_out) {
                v0 = tf32f(v0); v1 = tf32f(v1);
                v2 = tf32f(v2); v3 = tf32f(v3);
            }
            *reinterpret_cast<float2*>(C + (size_t)row0 * ldc + col)     = make_float2(v0, v1);
            *reinterpret_cast<float2*>(C + (size_t)(row0+8) * ldc + col) = make_float2(v2, v3);
        }
    }
}

// ---------------------------------------------------------------------------
// Pipelined TF32 score GEMM: per (b,h) S = Q @ K^T * scale + mask
// Q,K pre-rounded -> zero CVTs. CTA 128x128, K=64, warps 2m x 4n.
// grid (4 ntile, 4 mtile, 32 bh)
// ---------------------------------------------------------------------------
__global__ __launch_bounds__(256, 2) void score_tf32p(
    const float* __restrict__ Q,
    const float* __restrict__ Kmat,
    const int* __restrict__ x,
    float* __restrict__ attn, int l, float scale)
{
    constexpr int MI = 4, NI = 4;

    extern __shared__ float dsm[];
    float (*As)[128][20] = reinterpret_cast<float(*)[128][20]>(dsm);
    float (*Bs)[128][20] = reinterpret_cast<float(*)[128][20]>(dsm + 4*128*20);

    int tid  = threadIdx.x;
    int lane = tid & 31, warp = tid >> 5;
    int g    = lane >> 2, tig = lane & 3;
    int mw   = warp & 1, nw = warp >> 1;
    int wm   = mw * 64;
    int wn   = nw * 32;
    int zz = blockIdx.z;
    int b = zz >> 3, hh = zz & 7;
    int m0 = blockIdx.y * 128, n0 = blockIdx.x * 128;

    const float* Abase = Q    + (size_t)b*SS*DD + hh*DKV;
    const float* Bbase = Kmat + (size_t)b*SS*DD + hh*DKV;
    float* out = attn + (((size_t)b*LL + l)*HH + hh) * (size_t)(SS*SS);

    int arow = tid >> 1, acol = (tid & 1) * 8;

    const float* Aptr = Abase + (size_t)(m0 + arow) * DD + acol;
    const float* Bptr = Bbase + (size_t)(n0 + arow) * DD + acol;

    float acc[MI][NI][4];
#pragma unroll
    for (int mi = 0; mi < MI; mi++)
#pragma unroll
        for (int ni = 0; ni < NI; ni++)
#pragma unroll
            for (int r = 0; r < 4; r++) acc[mi][ni][r] = 0.f;

    const int nk = DKV >> 4; // 4

#pragma unroll
    for (int s = 0; s < 3; s++) {
        int k0 = s * 16;
        cp16(&As[s][arow][acol],     Aptr + k0);
        cp16(&As[s][arow][acol + 4], Aptr + k0 + 4);
        cp16(&Bs[s][arow][acol],     Bptr + k0);
        cp16(&Bs[s][arow][acol + 4], Bptr + k0 + 4);
        CP_COMMIT();
    }

#pragma unroll
    for (int it = 0; it < nk; it++) {
        if (it + 2 < nk) CP_WAIT2();
        else if (it + 1 < nk) CP_WAIT1();
        else CP_WAIT0();
        __syncthreads();
        int s = it & 3;
#pragma unroll
        for (int kk = 0; kk < 16; kk += 8) {
            uint32_t af[MI][4], bf[NI][2];
#pragma unroll
            for (int mi = 0; mi < MI; mi++) {
                int r = wm + mi*16 + g;
                af[mi][0] = ldraw(As[s][r    ][kk+tig  ]);
                af[mi][1] = ldraw(As[s][r + 8][kk+tig  ]);
                af[mi][2] = ldraw(As[s][r    ][kk+tig+4]);
                af[mi][3] = ldraw(As[s][r + 8][kk+tig+4]);
            }
#pragma unroll
            for (int ni = 0; ni < NI; ni++) {
                int cc = wn + ni*8 + g;
                bf[ni][0] = ldraw(Bs[s][cc][kk+tig  ]);
                bf[ni][1] = ldraw(Bs[s][cc][kk+tig+4]);
            }
#pragma unroll
            for (int mi = 0; mi < MI; mi++)
#pragma unroll
                for (int ni = 0; ni < NI; ni++)
                    mma_tf32(acc[mi][ni], af[mi], bf[ni]);
        }
        int nx = it + 3;
        if (nx < nk) {
            int sn = nx & 3;
            int k0 = nx * 16;
            cp16(&As[sn][arow][acol],     Aptr + k0);
            cp16(&As[sn][arow][acol + 4], Aptr + k0 + 4);
            cp16(&Bs[sn][arow][acol],     Bptr + k0);
            cp16(&Bs[sn][arow][acol + 4], Bptr + k0 + 4);
            CP_COMMIT();
        }
    }

    const int* xb = x + b*SS;
#pragma unroll
    for (int mi = 0; mi < MI; mi++) {
        int row0 = m0 + wm + mi*16 + g;
#pragma unroll
        for (int ni = 0; ni < NI; ni++) {
            int col = n0 + wn + ni*8 + 2*tig;
            bool msk0 = (xb[col]   == 0);
            bool msk1 = (xb[col+1] == 0);
            float v0 = msk0 ? -1e9f : acc[mi][ni][0] * scale;
            float v1 = msk1 ? -1e9f : acc[mi][ni][1] * scale;
            float v2 = msk0 ? -1e9f : acc[mi][ni][2] * scale;
            float v3 = msk1 ? -1e9f : acc[mi][ni][3] * scale;
            *reinterpret_cast<float2*>(out + (size_t)row0 * SS + col)     = make_float2(v0, v1);
            *reinterpret_cast<float2*>(out + (size_t)(row0+8) * SS + col) = make_float2(v2, v3);
        }
    }
}

// ---------------------------------------------------------------------------
// Pipelined TF32 ctx GEMM: per (b,h) C[512,64] = P[512,512] @ V[512,64]
// P pre-rounded by softmax -> raw; V pre-rounded -> raw. Output rounded.
// CTA 128x64, warps 4m x 2n. grid (4 mtile, 32 bh)
// ---------------------------------------------------------------------------
__global__ __launch_bounds__(256, 2) void ctx_tf32p(
    const float* __restrict__ attn,
    const float* __restrict__ V,
    float* __restrict__ C, int l)
{
    constexpr int MI = 2, NI = 4;

    extern __shared__ float dsm[];
    float (*As)[128][20] = reinterpret_cast<float(*)[128][20]>(dsm);
    float (*Bs)[16][72]  = reinterpret_cast<float(*)[16][72]>(dsm + 4*128*20);

    int tid  = threadIdx.x;
    int lane = tid & 31, warp = tid >> 5;
    int g    = lane >> 2, tig = lane & 3;
    int wm   = (warp & 3) * 32;
    int wn   = (warp >> 2) * 32;
    int zz = blockIdx.y;
    int b = zz >> 3, hh = zz & 7;
    int m0 = blockIdx.x * 128;

    const float* Abase = attn + (((size_t)b*LL + l)*HH + hh) * (size_t)(SS*SS);
    const float* Bbase = V + (size_t)b*SS*DD + hh*DKV;
    float* Cb = C + (size_t)b*SS*DD + hh*DKV;

    int arow = tid >> 1, acol = (tid & 1) * 8;
    int brow = tid >> 4, bcol = (tid & 15) * 4;

    const float* Aptr = Abase + (size_t)(m0 + arow) * SS + acol;
    const float* Bptr = Bbase + (size_t)brow * DD + bcol;

    float acc[MI][NI][4];
#pragma unroll
    for (int mi = 0; mi < MI; mi++)
#pragma unroll
        for (int ni = 0; ni < NI; ni++)
#pragma unroll
            for (int r = 0; r < 4; r++) acc[mi][ni][r] = 0.f;

    const int nk = SS >> 4; // 32

#pragma unroll
    for (int s = 0; s < 3; s++) {
        int k0 = s * 16;
        cp16(&As[s][arow][acol],     Aptr + k0);
        cp16(&As[s][arow][acol + 4], Aptr + k0 + 4);
        cp16(&Bs[s][brow][bcol],     Bptr + (size_t)k0 * DD);
        CP_COMMIT();
    }

    for (int it = 0; it < nk; it++) {
        if (it + 2 < nk) CP_WAIT2();
        else if (it + 1 < nk) CP_WAIT1();
        else CP_WAIT0();
        __syncthreads();
        int s = it & 3;
#pragma unroll
        for (int kk = 0; kk < 16; kk += 8) {
            uint32_t af[MI][4], bf[NI][2];
#pragma unroll
            for (int mi = 0; mi < MI; mi++) {
                int r = wm + mi*16 + g;
                af[mi][0] = ldraw(As[s][r    ][kk+tig  ]);
                af[mi][1] = ldraw(As[s][r + 8][kk+tig  ]);
                af[mi][2] = ldraw(As[s][r    ][kk+tig+4]);
                af[mi][3] = ldraw(As[s][r + 8][kk+tig+4]);
            }
#pragma unroll
            for (int ni = 0; ni < NI; ni++) {
                int cc = wn + ni*8 + g;
                bf[ni][0] = ldraw(Bs[s][kk+tig  ][cc]);
                bf[ni][1] = ldraw(Bs[s][kk+tig+4][cc]);
            }
#pragma unroll
            for (int mi = 0; mi < MI; mi++)
#pragma unroll
                for (int ni = 0; ni < NI; ni++)
                    mma_tf32(acc[mi][ni], af[mi], bf[ni]);
        }
        int nx = it + 3;
        if (nx < nk) {
            int sn = nx & 3;
            int k0 = nx * 16;
            cp16(&As[sn][arow][acol],     Aptr + k0);
            cp16(&As[sn][arow][acol + 4], Aptr + k0 + 4);
            cp16(&Bs[sn][brow][bcol],     Bptr + (size_t)k0 * DD);
            CP_COMMIT();
        }
    }

#pragma unroll
    for (int mi = 0; mi < MI; mi++) {
        int row0 = m0 + wm + mi*16 + g;
#pragma unroll
        for (int ni = 0; ni < NI; ni++) {
            int col = wn + ni*8 + 2*tig;
            *reinterpret_cast<float2*>(Cb + (size_t)row0 * DD + col)
                = make_float2(tf32f(acc[mi][ni][0]), tf32f(acc[mi][ni][1]));
            *reinterpret_cast<float2*>(Cb + (size_t)(row0+8) * DD + col)
                = make_float2(tf32f(acc[mi][ni][2]), tf32f(acc[mi][ni][3]));
        }
    }
}

// ---------------------------------------------------------------------------
// Softmax in-place, vectorized; outputs tf32-rounded (ctx reads raw bits)
// ---------------------------------------------------------------------------
__global__ __launch_bounds__(128) void softmax_kernel(float* __restrict__ attn, int l)
{
    __shared__ float red[8];
    int row = blockIdx.x;
    int b = row >> 12;
    int rem = row & 4095;
    float4* p = reinterpret_cast<float4*>(
        attn + (size_t)b*(LL*HH*SS*SS) + (size_t)l*(HH*SS*SS) + (size_t)rem*SS);
    int t = threadIdx.x;
    int lane = t & 31, wid = t >> 5;

    float4 v = p[t];

    float mx = fmaxf(fmaxf(v.x, v.y), fmaxf(v.z, v.w));
#pragma unroll
    for (int o = 16; o > 0; o >>= 1) mx = fmaxf(mx, __shfl_xor_sync(0xffffffffu, mx, o));
    if (lane == 0) red[wid] = mx;
    __syncthreads();
    mx = fmaxf(fmaxf(red[0],red[1]), fmaxf(red[2],red[3]));

    v.x = __expf(v.x - mx); v.y = __expf(v.y - mx);
    v.z = __expf(v.z - mx); v.w = __expf(v.w - mx);
    float s = v.x + v.y + v.z + v.w;
#pragma unroll
    for (int o = 16; o > 0; o >>= 1) s += __shfl_xor_sync(0xffffffffu, s, o);
    if (lane == 0) red[4 + wid] = s;
    __syncthreads();
    s = red[4] + red[5] + red[6] + red[7];
    float inv = 1.0f / s;
    v.x = tf32f(v.x * inv); v.y = tf32f(v.y * inv);
    v.z = tf32f(v.z * inv); v.w = tf32f(v.w * inv);
    p[t] = v;
}

// ---------------------------------------------------------------------------
// LayerNorm: 2 rows per 256-thread block, float4 per thread.
// ---------------------------------------------------------------------------
__global__ __launch_bounds__(256) void ln_kernel(
    const float* __restrict__ in,
    const float* __restrict__ g,
    const float* __restrict__ bta,
    float* __restrict__ outh,
    float* __restrict__ outhr)
{
    __shared__ float red[2][8];
    int half = threadIdx.x >> 7;
    int row  = blockIdx.x * 2 + half;
    int t    = threadIdx.x & 127;
    int lane = t & 31, wid = t >> 5;

    const float4* p = reinterpret_cast<const float4*>(in + (size_t)row*DD);
    float4 v = p[t];

    float s  = v.x + v.y + v.z + v.w;
    float sq = v.x*v.x + v.y*v.y + v.z*v.z + v.w*v.w;
#pragma unroll
    for (int o = 16; o > 0; o >>= 1) {
        s  += __shfl_xor_sync(0xffffffffu, s,  o);
        sq += __shfl_xor_sync(0xffffffffu, sq, o);
    }
    if (lane == 0) { red[half][wid] = s; red[half][4+wid] = sq; }
    __syncthreads();
    s  = red[half][0]+red[half][1]+red[half][2]+red[half][3];
    sq = red[half][4]+red[half][5]+red[half][6]+red[half][7];
    float mu = s * (1.0f/DD);
    float var = sq * (1.0f/DD) - mu*mu;
    float rstd = rsqrtf(var + EPS);

    float4 gg = reinterpret_cast<const float4*>(g)[t];
    float4 bb = reinterpret_cast<const float4*>(bta)[t];
    float4 r;
    r.x = (v.x - mu) * rstd * gg.x + bb.x;
    r.y = (v.y - mu) * rstd * gg.y + bb.y;
    r.z = (v.z - mu) * rstd * gg.z + bb.z;
    r.w = (v.w - mu) * rstd * gg.w + bb.w;
    reinterpret_cast<float4*>(outh + (size_t)row*DD)[t] = r;
    if (outhr) {
        float4 rr; rr.x=tf32f(r.x); rr.y=tf32f(r.y); rr.z=tf32f(r.z); rr.w=tf32f(r.w);
        reinterpret_cast<float4*>(outhr + (size_t)row*DD)[t] = rr;
    }
}

// ---------------------------------------------------------------------------
extern "C" void kernel_launch(void* const* d_in, const int* in_sizes, int n_in,
                              void* d_out, int out_size)
{
    const int*   x    = (const int*)  d_in[0];
    const float* emb  = (const float*)d_in[1];
    const float* pe   = (const float*)d_in[2];
    const float* WQ   = (const float*)d_in[3];
    const float* bQ   = (const float*)d_in[4];
    const float* WK   = (const float*)d_in[5];
    const float* bK   = (const float*)d_in[6];
    const float* WV   = (const float*)d_in[7];
    const float* bV   = (const float*)d_in[8];
    const float* WO   = (const float*)d_in[9];
    const float* bO   = (const float*)d_in[10];
    const float* ln1g = (const float*)d_in[11];
    const float* ln1b = (const float*)d_in[12];
    const float* W1   = (const float*)d_in[13];
    const float* b1   = (const float*)d_in[14];
    const float* W2   = (const float*)d_in[15];
    const float* b2   = (const float*)d_in[16];
    const float* ln2g = (const float*)d_in[17];
    const float* ln2b = (const float*)d_in[18];

    float* out  = (float*)d_out;
    float* attn = out + (size_t)NTOK*DD;

    float *h, *hr, *q, *k, *v, *ctx, *tmp, *ff;
    float *wq, *wk, *wv, *wo, *w1, *w2;
    cudaGetSymbolAddress((void**)&h,   g_h);
    cudaGetSymbolAddress((void**)&hr,  g_hr);
    cudaGetSymbolAddress((void**)&q,   g_q);
    cudaGetSymbolAddress((void**)&k,   g_k);
    cudaGetSymbolAddress((void**)&v,   g_v);
    cudaGetSymbolAddress((void**)&ctx, g_ctx);
    cudaGetSymbolAddress((void**)&tmp, g_tmp);
    cudaGetSymbolAddress((void**)&ff,  g_ff);
    cudaGetSymbolAddress((void**)&wq,  g_wq);
    cudaGetSymbolAddress((void**)&wk,  g_wk);
    cudaGetSymbolAddress((void**)&wv,  g_wv);
    cudaGetSymbolAddress((void**)&wo,  g_wo);
    cudaGetSymbolAddress((void**)&w1,  g_w1);
    cudaGetSymbolAddress((void**)&w2,  g_w2);

    // dynamic smem sizes (bytes)
    const int SM_D128 = (4*128*20 + 4*16*136) * 4;  // 75776
    const int SM_D64  = (4*128*20 + 4*16*72)  * 4;  // 59392
    const int SM_SC   = (4*128*20 + 4*128*20) * 4;  // 81920

    static int init_done = 0;
    static cudaStream_t s1;
    static cudaEvent_t evF, evJ;
    if (!init_done) {
        cudaFuncSetAttribute(gemm_tf32p<128,2>, cudaFuncAttributeMaxDynamicSharedMemorySize, SM_D128);
        cudaFuncSetAttribute(gemm_tf32p<64,4>,  cudaFuncAttributeMaxDynamicSharedMemorySize, SM_D64);
        cudaFuncSetAttribute(score_tf32p,       cudaFuncAttributeMaxDynamicSharedMemorySize, SM_SC);
        cudaFuncSetAttribute(ctx_tf32p,         cudaFuncAttributeMaxDynamicSharedMemorySize, SM_D64);
        cudaStreamCreateWithFlags(&s1, cudaStreamNonBlocking);
        cudaEventCreateWithFlags(&evF, cudaEventDisableTiming);
        cudaEventCreateWithFlags(&evJ, cudaEventDisableTiming);
        init_done = 1;
    }

    const float scale = 0.125f;

    // pre-round all weights to tf32 (once per call)
    {
        int n4s = LL*DD*DD/4;    // 393216
        int n4f = LL*DD*DFF/4;   // 1572864
        roundw_kernel<<<(n4s+255)/256, 256>>>((const float4*)WQ, (float4*)wq, n4s);
        roundw_kernel<<<(n4s+255)/256, 256>>>((const float4*)WK, (float4*)wk, n4s);
        roundw_kernel<<<(n4s+255)/256, 256>>>((const float4*)WV, (float4*)wv, n4s);
        roundw_kernel<<<(n4s+255)/256, 256>>>((const float4*)WO, (float4*)wo, n4s);
        roundw_kernel<<<(n4f+255)/256, 256>>>((const float4*)W1, (float4*)w1, n4f);
        roundw_kernel<<<(n4f+255)/256, 256>>>((const float4*)W2, (float4*)w2, n4f);
    }

    embed_kernel<<<NTOK, 128>>>(x, emb, pe, h, hr);

    for (int l = 0; l < LL; l++) {
        const float* wql = wq + (size_t)l*DD*DD;
        const float* wkl = wk + (size_t)l*DD*DD;
        const float* wvl = wv + (size_t)l*DD*DD;
        const float* wol = wo + (size_t)l*DD*DD;
        const float* w1l = w1 + (size_t)l*DD*DFF;
        const float* w2l = w2 + (size_t)l*DFF*DD;

        // QK projection on main stream (z=2)
        gemm_tf32p<128,2><<<dim3(4,16,2), 256, SM_D128>>>(hr, DD,
            wql, wkl, wkl, DD,
            bQ + l*DD, bK + l*DD, bK + l*DD,
            nullptr,
            q, k, k, DD, DD, 0, 1);

        // V projection on side stream, overlapped with score+softmax
        cudaEventRecord(evF, 0);
        cudaStreamWaitEvent(s1, evF, 0);
        gemm_tf32p<128,2><<<dim3(4,16,1), 256, SM_D128, s1>>>(hr, DD,
            wvl, wvl, wvl, DD,
            bV + l*DD, bV + l*DD, bV + l*DD,
            nullptr,
            v, v, v, DD, DD, 0, 1);
        cudaEventRecord(evJ, s1);

        score_tf32p<<<dim3(4,4,32), 256, SM_SC>>>(q, k, x, attn, l, scale);
        softmax_kernel<<<BB*HH*SS, 128>>>(attn, l);

        cudaStreamWaitEvent(0, evJ, 0);
        ctx_tf32p<<<dim3(4,32), 256, SM_D64>>>(attn, v, ctx, l);

        // WO: residual = fp32 h, out fp32 (feeds LN only)
        gemm_tf32p<64,4><<<dim3(8,16,1), 256, SM_D64>>>(ctx, DD,
            wol, wol, wol, DD,
            bO + l*DD, bO + l*DD, bO + l*DD,
            h,
            tmp, tmp, tmp, DD, DD, 0, 0);
        ln_kernel<<<NTOK/2, 256>>>(tmp, ln1g + l*DD, ln1b + l*DD, h, hr);

        // FFN1: output ff rounded (feeds FFN2 A raw)
        gemm_tf32p<128,2><<<dim3(16,16,1), 256, SM_D128>>>(hr, DD,
            w1l, w1l, w1l, DFF,
            b1 + l*DFF, b1 + l*DFF, b1 + l*DFF,
            nullptr,
            ff, ff, ff, DFF, DD, 1, 1);

        // FFN2: residual = fp32 h, out fp32
        gemm_tf32p<64,4><<<dim3(8,16,1), 256, SM_D64>>>(ff, DFF,
            w2l, w2l, w2l, DD,
            b2 + l*DD, b2 + l*DD, b2 + l*DD,
            h,
            tmp, tmp, tmp, DD, DFF, 0, 0);

        if (l == LL-1) {
            ln_kernel<<<NTOK/2, 256>>>(tmp, ln2g + l*DD, ln2b + l*DD, out, nullptr);
        } else {
            ln_kernel<<<NTOK/2, 256>>>(tmp, ln2g + l*DD, ln2b + l*DD, h, hr);
        }
    }
}